// round 10
// baseline (speedup 1.0000x reference)
#include <cuda_runtime.h>
#include <float.h>

// Problem constants (fixed by reference setup_inputs)
#define N_PTS 8192
#define C_CH  256
#define KNN   16

typedef unsigned long long u64;

// ---------------- packed-fp32 (FFMA2) helpers --------------------------------
__device__ __forceinline__ void fma2(u64 &acc, u64 a, u64 b) {
    asm("fma.rn.f32x2 %0, %1, %2, %0;" : "+l"(acc) : "l"(a), "l"(b));
}
__device__ __forceinline__ u64 bcast2(float v) {
    u64 r;
    asm("mov.b64 %0, {%1, %2};" : "=l"(r) : "f"(v), "f"(v));
    return r;
}
__device__ __forceinline__ u64 pack2(float lo, float hi) {
    u64 r;
    asm("mov.b64 %0, {%1, %2};" : "=l"(r) : "f"(lo), "f"(hi));
    return r;
}
__device__ __forceinline__ void unpack2(u64 v, float &lo, float &hi) {
    asm("mov.b64 {%0, %1}, %2;" : "=f"(lo), "=f"(hi) : "l"(v));
}

// ---------------- scratch (device globals; no allocation allowed) ----------
__device__ float4 g_xyzs[N_PTS];            // x,y,z, |p|^2
__device__ int    g_idx[N_PTS * KNN];       // knn indices
__device__ float  g_theta[N_PTS * C_CH];    // feats @ theta_w + b
__device__ float  g_phi  [N_PTS * C_CH];    // feats @ phi_w + b
__device__ float  g_gv   [N_PTS * C_CH];    // feats @ g_w + b
__device__ float  g_y    [N_PTS * C_CH];    // attention output

// ---------------------------------------------------------------------------
// 1) pack coords + squared norms
// ---------------------------------------------------------------------------
__global__ __launch_bounds__(256) void prep_kernel(const float* __restrict__ coords) {
    int i = blockIdx.x * blockDim.x + threadIdx.x;
    if (i < N_PTS) {
        float x = coords[i * 3 + 0], y = coords[i * 3 + 1], z = coords[i * 3 + 2];
        g_xyzs[i] = make_float4(x, y, z, x * x + y * y + z * z);
    }
}

// ---------------------------------------------------------------------------
// 2) KNN (unchanged): one block per query point, 16x argmin w/ cached minima.
// ---------------------------------------------------------------------------
__global__ __launch_bounds__(256) void knn_kernel() {
    __shared__ float sd[N_PTS];       // 32 KB
    __shared__ float wmin[8];
    __shared__ int   warg[8];
    __shared__ int   s_win;

    const int i   = blockIdx.x;
    const int tid = threadIdx.x;
    const float4 q = g_xyzs[i];

    float lmin = FLT_MAX;
    int   larg = 0x7fffffff;
    for (int j = tid; j < N_PTS; j += 256) {
        float4 p = g_xyzs[j];
        float d = q.w + p.w - 2.0f * (q.x * p.x + q.y * p.y + q.z * p.z);
        sd[j] = d;
        if (d < lmin || (d == lmin && j < larg)) { lmin = d; larg = j; }
    }
    __syncthreads();

    const int lane = tid & 31, wid = tid >> 5;
    for (int it = 0; it < KNN; it++) {
        float v = lmin; int a = larg;
        #pragma unroll
        for (int off = 16; off > 0; off >>= 1) {
            float ov = __shfl_down_sync(0xffffffffu, v, off);
            int   oa = __shfl_down_sync(0xffffffffu, a, off);
            if (ov < v || (ov == v && oa < a)) { v = ov; a = oa; }
        }
        if (lane == 0) { wmin[wid] = v; warg[wid] = a; }
        __syncthreads();
        if (tid == 0) {
            float bv = wmin[0]; int ba = warg[0];
            #pragma unroll
            for (int w = 1; w < 8; w++)
                if (wmin[w] < bv || (wmin[w] == bv && warg[w] < ba)) { bv = wmin[w]; ba = warg[w]; }
            s_win = ba;
            g_idx[i * KNN + it] = ba;
        }
        __syncthreads();
        const int wa = s_win;
        if ((wa & 255) == tid) {
            sd[wa] = FLT_MAX;
            lmin = FLT_MAX; larg = 0x7fffffff;
            for (int j = tid; j < N_PTS; j += 256) {
                float d = sd[j];
                if (d < lmin || (d == lmin && j < larg)) { lmin = d; larg = j; }
            }
        }
    }
}

// ---------------------------------------------------------------------------
// 3) C[M,N] = A[M,256] @ B[256,N] + bias (+ residual). 64x64 tile, BK=16.
//    B stored DUPLICATED in smem (each value twice adjacent) so one LDS.128
//    yields two broadcast u64 operands -> zero bcast MOVs in inner loop.
// ---------------------------------------------------------------------------
__global__ __launch_bounds__(256) void gemm64_kernel(const float* __restrict__ A,
                                                     const float* __restrict__ B,
                                                     const float* __restrict__ bias,
                                                     const float* __restrict__ resid,
                                                     float* __restrict__ C) {
    __shared__ float As[16][68];    // [k][row], stride 272B (16B-aligned)
    __shared__ float Bs2[16][128];  // [k][col duplicated]

    const int tid  = threadIdx.x;
    const int row0 = blockIdx.y * 64;
    const int col0 = blockIdx.x * 64;
    const int tx = tid & 15, ty = tid >> 4;
    const int ar = tid >> 2, ak = (tid & 3) * 4;
    const int br = tid >> 4, bc = (tid & 15) * 4;

    u64 acc[2][4];                 // [row-pair][col]
    #pragma unroll
    for (int rp = 0; rp < 2; rp++)
        #pragma unroll
        for (int c = 0; c < 4; c++) acc[rp][c] = 0ull;

    for (int k0 = 0; k0 < 256; k0 += 16) {
        float4 av = *(const float4*)&A[(row0 + ar) * 256 + k0 + ak];
        float4 bv = *(const float4*)&B[(k0 + br) * 256 + col0 + bc];
        As[ak + 0][ar] = av.x; As[ak + 1][ar] = av.y;
        As[ak + 2][ar] = av.z; As[ak + 3][ar] = av.w;
        *(float4*)&Bs2[br][bc * 2]     = make_float4(bv.x, bv.x, bv.y, bv.y);
        *(float4*)&Bs2[br][bc * 2 + 4] = make_float4(bv.z, bv.z, bv.w, bv.w);
        __syncthreads();
        #pragma unroll
        for (int kk = 0; kk < 16; kk++) {
            const ulonglong2 a  = *(const ulonglong2*)&As[kk][ty * 4];
            const ulonglong2 b0 = *(const ulonglong2*)&Bs2[kk][tx * 8];
            const ulonglong2 b1 = *(const ulonglong2*)&Bs2[kk][tx * 8 + 4];
            fma2(acc[0][0], a.x, b0.x); fma2(acc[0][1], a.x, b0.y);
            fma2(acc[0][2], a.x, b1.x); fma2(acc[0][3], a.x, b1.y);
            fma2(acc[1][0], a.y, b0.x); fma2(acc[1][1], a.y, b0.y);
            fma2(acc[1][2], a.y, b1.x); fma2(acc[1][3], a.y, b1.y);
        }
        __syncthreads();
    }

    const int col = col0 + tx * 4;
    const float4 bz = *(const float4*)&bias[col];
    #pragma unroll
    for (int rp = 0; rp < 2; rp++) {
        const int rA = row0 + ty * 4 + rp * 2;
        float l0, h0, l1, h1, l2, h2, l3, h3;
        unpack2(acc[rp][0], l0, h0); unpack2(acc[rp][1], l1, h1);
        unpack2(acc[rp][2], l2, h2); unpack2(acc[rp][3], l3, h3);
        float4 oA = make_float4(l0 + bz.x, l1 + bz.y, l2 + bz.z, l3 + bz.w);
        float4 oB = make_float4(h0 + bz.x, h1 + bz.y, h2 + bz.z, h3 + bz.w);
        if (resid) {
            const float4 rv = *(const float4*)&resid[rA * 256 + col];
            const float4 rw = *(const float4*)&resid[(rA + 1) * 256 + col];
            oA.x += rv.x; oA.y += rv.y; oA.z += rv.z; oA.w += rv.w;
            oB.x += rw.x; oB.y += rw.y; oB.z += rw.z; oB.w += rw.w;
        }
        *(float4*)&C[rA * 256 + col] = oA;
        *(float4*)&C[(rA + 1) * 256 + col] = oB;
    }
}

// ---------------------------------------------------------------------------
// 4) batched attention: 8 points x 64 cols per block (grid 4 x 1024).
//    M=128 rows (point,k), N=64 cols, K=256. 8x4 microtile, FFMA2 row pairs,
//    duplicated w2 in smem (no bcast MOVs). 2 blocks/SM via launch_bounds.
// ---------------------------------------------------------------------------
__global__ __launch_bounds__(256, 2) void attn_kernel(const float* __restrict__ coords,
                                                      const float* __restrict__ w1,
                                                      const float* __restrict__ b1,
                                                      const float* __restrict__ w2,
                                                      const float* __restrict__ b2) {
    __shared__ float As[16][132];     // [k][row], stride 528B (16B-aligned)
    __shared__ float Bs[16][128];     // [k][col duplicated]  (64 cols x2)
    __shared__ float sdc[128 * 3];    // delta coords per row
    __shared__ int   sidx[128];       // neighbor ids per row
    __shared__ float sw1[3 * 256];
    __shared__ float sb1[256];

    const int t  = threadIdx.x;
    const int p0 = blockIdx.y * 8;          // first point of block
    const int cb = blockIdx.x * 64;         // column base
    const int tx = t & 15, ty = t >> 4;

    if (t < 192) ((float4*)sw1)[t] = ((const float4*)w1)[t];
    if (t < 64)  ((float4*)sb1)[t] = ((const float4*)b1)[t];
    if (t < 128) {
        const int p = t >> 4;
        const int nn = g_idx[(p0 + p) * 16 + (t & 15)];
        sidx[t] = nn;
        sdc[t * 3 + 0] = coords[nn * 3 + 0] - coords[(p0 + p) * 3 + 0];
        sdc[t * 3 + 1] = coords[nn * 3 + 1] - coords[(p0 + p) * 3 + 1];
        sdc[t * 3 + 2] = coords[nn * 3 + 2] - coords[(p0 + p) * 3 + 2];
    }
    __syncthreads();

    // dc registers for generation rows (tx*8 .. tx*8+7); fixed across k0
    float dcx[8], dcy[8], dcz[8];
    #pragma unroll
    for (int r = 0; r < 8; r++) {
        dcx[r] = sdc[(tx * 8 + r) * 3 + 0];
        dcy[r] = sdc[(tx * 8 + r) * 3 + 1];
        dcz[r] = sdc[(tx * 8 + r) * 3 + 2];
    }

    // accumulators: 4 row-pairs x 4 cols (cols cb + tx*4 + 0..3)
    u64 acc[4][4];
    {
        const float4 bA = *(const float4*)&b2[cb + tx * 4];
        const float bv[4] = {bA.x, bA.y, bA.z, bA.w};
        #pragma unroll
        for (int rp = 0; rp < 4; rp++)
            #pragma unroll
            for (int j = 0; j < 4; j++) acc[rp][j] = bcast2(bv[j]);
    }

    const float* w2p = w2 + cb;

    for (int k0 = 0; k0 < 256; k0 += 16) {
        // generate hidden tile: thread handles kk=ty, rows tx*8..+7
        {
            const int kc = k0 + ty;
            const float wx = sw1[kc], wy = sw1[256 + kc], wz = sw1[512 + kc];
            const float bb = sb1[kc];
            float h[8];
            #pragma unroll
            for (int r = 0; r < 8; r++)
                h[r] = fmaxf(fmaf(dcz[r], wz, fmaf(dcy[r], wy, fmaf(dcx[r], wx, bb))), 0.0f);
            *(float4*)&As[ty][tx * 8]     = make_float4(h[0], h[1], h[2], h[3]);
            *(float4*)&As[ty][tx * 8 + 4] = make_float4(h[4], h[5], h[6], h[7]);
        }
        // load w2 tile (16 x 64), store duplicated: col c at positions 2c, 2c+1
        {
            const int kk2 = t >> 4, cq = (t & 15) * 4;
            const float4 v = *(const float4*)&w2p[(k0 + kk2) * 256 + cq];
            *(float4*)&Bs[kk2][cq * 2]     = make_float4(v.x, v.x, v.y, v.y);
            *(float4*)&Bs[kk2][cq * 2 + 4] = make_float4(v.z, v.z, v.w, v.w);
        }
        __syncthreads();
        #pragma unroll
        for (int kk = 0; kk < 16; kk++) {
            const ulonglong2 a01 = *(const ulonglong2*)&As[kk][ty * 8];
            const ulonglong2 a23 = *(const ulonglong2*)&As[kk][ty * 8 + 4];
            const ulonglong2 b0  = *(const ulonglong2*)&Bs[kk][tx * 8];
            const ulonglong2 b1  = *(const ulonglong2*)&Bs[kk][tx * 8 + 4];
            fma2(acc[0][0], a01.x, b0.x); fma2(acc[0][1], a01.x, b0.y);
            fma2(acc[0][2], a01.x, b1.x); fma2(acc[0][3], a01.x, b1.y);
            fma2(acc[1][0], a01.y, b0.x); fma2(acc[1][1], a01.y, b0.y);
            fma2(acc[1][2], a01.y, b1.x); fma2(acc[1][3], a01.y, b1.y);
            fma2(acc[2][0], a23.x, b0.x); fma2(acc[2][1], a23.x, b0.y);
            fma2(acc[2][2], a23.x, b1.x); fma2(acc[2][3], a23.x, b1.y);
            fma2(acc[3][0], a23.y, b0.x); fma2(acc[3][1], a23.y, b0.y);
            fma2(acc[3][2], a23.y, b1.x); fma2(acc[3][3], a23.y, b1.y);
        }
        __syncthreads();
    }

    // ---------------- epilogue: df -> softmax(K) -> y, all in registers ----
    // warp w owns point p0+w (rows 16w..16w+15). lanes 0-15: k 0-7; 16-31: k 8-15.
    const int w = t >> 5;
    const int i = p0 + w;
    const int half = (t >> 4) & 1;
    const int kbase = half * 8;

    float th[4];
    {
        const float4 tA = *(const float4*)&g_theta[i * 256 + cb + tx * 4];
        th[0] = tA.x; th[1] = tA.y; th[2] = tA.z; th[3] = tA.w;
    }

    float mx[4];
    #pragma unroll
    for (int j = 0; j < 4; j++) mx[j] = -FLT_MAX;

    // pass 1: delta features (in place), track max over own 8 k
    #pragma unroll
    for (int rp = 0; rp < 4; rp++) {
        const int nl = sidx[w * 16 + kbase + rp * 2];
        const int nh = sidx[w * 16 + kbase + rp * 2 + 1];
        const float4 lA = *(const float4*)&g_phi[nl * 256 + cb + tx * 4];
        const float4 hA = *(const float4*)&g_phi[nh * 256 + cb + tx * 4];
        const float pl[4] = {lA.x, lA.y, lA.z, lA.w};
        const float ph[4] = {hA.x, hA.y, hA.z, hA.w};
        #pragma unroll
        for (int j = 0; j < 4; j++) {
            float lo, hi;
            unpack2(acc[rp][j], lo, hi);
            lo = lo * (th[j] - pl[j] + 1.0f) * 0.0625f;
            hi = hi * (th[j] - ph[j] + 1.0f) * 0.0625f;
            mx[j] = fmaxf(mx[j], fmaxf(lo, hi));
            acc[rp][j] = pack2(lo, hi);
        }
    }
    #pragma unroll
    for (int j = 0; j < 4; j++)
        mx[j] = fmaxf(mx[j], __shfl_xor_sync(0xffffffffu, mx[j], 16));

    float ssum[4], gac[4];
    #pragma unroll
    for (int j = 0; j < 4; j++) { ssum[j] = 0.0f; gac[j] = 0.0f; }

    // pass 2: exp + weighted g accumulation
    #pragma unroll
    for (int rp = 0; rp < 4; rp++) {
        const int nl = sidx[w * 16 + kbase + rp * 2];
        const int nh = sidx[w * 16 + kbase + rp * 2 + 1];
        const float4 lA = *(const float4*)&g_gv[nl * 256 + cb + tx * 4];
        const float4 hA = *(const float4*)&g_gv[nh * 256 + cb + tx * 4];
        const float gl[4] = {lA.x, lA.y, lA.z, lA.w};
        const float gh[4] = {hA.x, hA.y, hA.z, hA.w};
        #pragma unroll
        for (int j = 0; j < 4; j++) {
            float lo, hi;
            unpack2(acc[rp][j], lo, hi);
            const float el = __expf(lo - mx[j]);
            const float eh = __expf(hi - mx[j]);
            ssum[j] += el + eh;
            gac[j] = fmaf(el, gl[j], fmaf(eh, gh[j], gac[j]));
        }
    }
    #pragma unroll
    for (int j = 0; j < 4; j++) {
        ssum[j] += __shfl_xor_sync(0xffffffffu, ssum[j], 16);
        gac[j]  += __shfl_xor_sync(0xffffffffu, gac[j], 16);
    }

    if (half == 0) {
        float4 oA = make_float4(gac[0] / ssum[0], gac[1] / ssum[1],
                                gac[2] / ssum[2], gac[3] / ssum[3]);
        *(float4*)&g_y[i * 256 + cb + tx * 4] = oA;
    }
}

// ---------------------------------------------------------------------------
extern "C" void kernel_launch(void* const* d_in, const int* in_sizes, int n_in,
                              void* d_out, int out_size) {
    const float* coords  = (const float*)d_in[0];
    const float* feats   = (const float*)d_in[1];
    const float* theta_w = (const float*)d_in[2];
    const float* theta_b = (const float*)d_in[3];
    const float* phi_w   = (const float*)d_in[4];
    const float* phi_b   = (const float*)d_in[5];
    const float* g_w     = (const float*)d_in[6];
    const float* g_b     = (const float*)d_in[7];
    const float* pe_w1   = (const float*)d_in[8];
    const float* pe_b1   = (const float*)d_in[9];
    const float* pe_w2   = (const float*)d_in[10];
    const float* pe_b2   = (const float*)d_in[11];
    const float* W_w     = (const float*)d_in[12];
    const float* W_b     = (const float*)d_in[13];
    float* out = (float*)d_out;

    float *p_theta, *p_phi, *p_gv, *p_y;
    cudaGetSymbolAddress((void**)&p_theta, g_theta);
    cudaGetSymbolAddress((void**)&p_phi,   g_phi);
    cudaGetSymbolAddress((void**)&p_gv,    g_gv);
    cudaGetSymbolAddress((void**)&p_y,     g_y);

    prep_kernel<<<(N_PTS + 255) / 256, 256>>>(coords);
    knn_kernel<<<N_PTS, 256>>>();

    dim3 ggrid(C_CH / 64, N_PTS / 64);
    gemm64_kernel<<<ggrid, 256>>>(feats, theta_w, theta_b, nullptr, p_theta);
    gemm64_kernel<<<ggrid, 256>>>(feats, phi_w,   phi_b,   nullptr, p_phi);
    gemm64_kernel<<<ggrid, 256>>>(feats, g_w,     g_b,     nullptr, p_gv);

    dim3 agrid(4, N_PTS / 8);
    attn_kernel<<<agrid, 256>>>(coords, pe_w1, pe_b1, pe_w2, pe_b2);

    gemm64_kernel<<<ggrid, 256>>>(p_y, W_w, W_b, feats, out);
}

// round 12
// speedup vs baseline: 1.1014x; 1.1014x over previous
#include <cuda_runtime.h>
#include <float.h>

// Problem constants (fixed by reference setup_inputs)
#define N_PTS 8192
#define C_CH  256
#define KNN   16

typedef unsigned long long u64;

// ---------------- packed-fp32 (FFMA2) helpers --------------------------------
__device__ __forceinline__ void fma2(u64 &acc, u64 a, u64 b) {
    asm("fma.rn.f32x2 %0, %1, %2, %0;" : "+l"(acc) : "l"(a), "l"(b));
}
__device__ __forceinline__ u64 bcast2(float v) {
    u64 r;
    asm("mov.b64 %0, {%1, %2};" : "=l"(r) : "f"(v), "f"(v));
    return r;
}
__device__ __forceinline__ u64 pack2(float lo, float hi) {
    u64 r;
    asm("mov.b64 %0, {%1, %2};" : "=l"(r) : "f"(lo), "f"(hi));
    return r;
}
__device__ __forceinline__ void unpack2(u64 v, float &lo, float &hi) {
    asm("mov.b64 {%0, %1}, %2;" : "=f"(lo), "=f"(hi) : "l"(v));
}

// ---------------- scratch (device globals; no allocation allowed) ----------
__device__ float4 g_xyzs[N_PTS];            // x,y,z, |p|^2
__device__ int    g_idx[N_PTS * KNN];       // knn indices
__device__ float  g_theta[N_PTS * C_CH];    // feats @ theta_w + b
__device__ float  g_phi  [N_PTS * C_CH];    // feats @ phi_w + b
__device__ float  g_gv   [N_PTS * C_CH];    // feats @ g_w + b
__device__ float  g_y    [N_PTS * C_CH];    // attention output

// ---------------------------------------------------------------------------
// 1) pack coords + squared norms
// ---------------------------------------------------------------------------
__global__ __launch_bounds__(256) void prep_kernel(const float* __restrict__ coords) {
    int i = blockIdx.x * blockDim.x + threadIdx.x;
    if (i < N_PTS) {
        float x = coords[i * 3 + 0], y = coords[i * 3 + 1], z = coords[i * 3 + 2];
        g_xyzs[i] = make_float4(x, y, z, x * x + y * y + z * z);
    }
}

// ---------------------------------------------------------------------------
// 2) KNN (R9, unchanged): one block per query point, 16x argmin.
// ---------------------------------------------------------------------------
__global__ __launch_bounds__(256) void knn_kernel() {
    __shared__ float sd[N_PTS];       // 32 KB
    __shared__ float wmin[8];
    __shared__ int   warg[8];
    __shared__ int   s_win;

    const int i   = blockIdx.x;
    const int tid = threadIdx.x;
    const float4 q = g_xyzs[i];

    float lmin = FLT_MAX;
    int   larg = 0x7fffffff;
    for (int j = tid; j < N_PTS; j += 256) {
        float4 p = g_xyzs[j];
        float d = q.w + p.w - 2.0f * (q.x * p.x + q.y * p.y + q.z * p.z);
        sd[j] = d;
        if (d < lmin || (d == lmin && j < larg)) { lmin = d; larg = j; }
    }
    __syncthreads();

    const int lane = tid & 31, wid = tid >> 5;
    for (int it = 0; it < KNN; it++) {
        float v = lmin; int a = larg;
        #pragma unroll
        for (int off = 16; off > 0; off >>= 1) {
            float ov = __shfl_down_sync(0xffffffffu, v, off);
            int   oa = __shfl_down_sync(0xffffffffu, a, off);
            if (ov < v || (ov == v && oa < a)) { v = ov; a = oa; }
        }
        if (lane == 0) { wmin[wid] = v; warg[wid] = a; }
        __syncthreads();
        if (tid == 0) {
            float bv = wmin[0]; int ba = warg[0];
            #pragma unroll
            for (int w = 1; w < 8; w++)
                if (wmin[w] < bv || (wmin[w] == bv && warg[w] < ba)) { bv = wmin[w]; ba = warg[w]; }
            s_win = ba;
            g_idx[i * KNN + it] = ba;
        }
        __syncthreads();
        const int wa = s_win;
        if ((wa & 255) == tid) {
            sd[wa] = FLT_MAX;
            lmin = FLT_MAX; larg = 0x7fffffff;
            for (int j = tid; j < N_PTS; j += 256) {
                float d = sd[j];
                if (d < lmin || (d == lmin && j < larg)) { lmin = d; larg = j; }
            }
        }
    }
}

// ---------------------------------------------------------------------------
// 3) C[M,N] = A[M,256] @ B[256,N] + bias (+ residual). 64x64 tile, BK=16.
//    R9 version (non-duplicated B; float4 + bcast MOVs — crossbar-light).
// ---------------------------------------------------------------------------
__global__ __launch_bounds__(256) void gemm64_kernel(const float* __restrict__ A,
                                                     const float* __restrict__ B,
                                                     const float* __restrict__ bias,
                                                     const float* __restrict__ resid,
                                                     float* __restrict__ C) {
    __shared__ float As[16][68];   // [k][row], stride 272B (16B-aligned)
    __shared__ float Bs[16][64];   // [k][col]

    const int tid  = threadIdx.x;
    const int row0 = blockIdx.y * 64;
    const int col0 = blockIdx.x * 64;
    const int tx = tid & 15, ty = tid >> 4;
    const int ar = tid >> 2, ak = (tid & 3) * 4;
    const int br = tid >> 4, bc = (tid & 15) * 4;

    u64 acc[2][4];                 // [row-pair][col]
    #pragma unroll
    for (int rp = 0; rp < 2; rp++)
        #pragma unroll
        for (int c = 0; c < 4; c++) acc[rp][c] = 0ull;

    for (int k0 = 0; k0 < 256; k0 += 16) {
        float4 av = *(const float4*)&A[(row0 + ar) * 256 + k0 + ak];
        float4 bv = *(const float4*)&B[(k0 + br) * 256 + col0 + bc];
        As[ak + 0][ar] = av.x; As[ak + 1][ar] = av.y;
        As[ak + 2][ar] = av.z; As[ak + 3][ar] = av.w;
        *(float4*)&Bs[br][bc] = bv;
        __syncthreads();
        #pragma unroll
        for (int kk = 0; kk < 16; kk++) {
            const ulonglong2 a = *(const ulonglong2*)&As[kk][ty * 4];
            const float4 b4 = *(const float4*)&Bs[kk][tx * 4];
            const u64 b0 = bcast2(b4.x), b1 = bcast2(b4.y);
            const u64 b2 = bcast2(b4.z), b3 = bcast2(b4.w);
            fma2(acc[0][0], a.x, b0); fma2(acc[0][1], a.x, b1);
            fma2(acc[0][2], a.x, b2); fma2(acc[0][3], a.x, b3);
            fma2(acc[1][0], a.y, b0); fma2(acc[1][1], a.y, b1);
            fma2(acc[1][2], a.y, b2); fma2(acc[1][3], a.y, b3);
        }
        __syncthreads();
    }

    const int col = col0 + tx * 4;
    const float4 bz = *(const float4*)&bias[col];
    #pragma unroll
    for (int rp = 0; rp < 2; rp++) {
        const int rA = row0 + ty * 4 + rp * 2;
        float l0, h0, l1, h1, l2, h2, l3, h3;
        unpack2(acc[rp][0], l0, h0); unpack2(acc[rp][1], l1, h1);
        unpack2(acc[rp][2], l2, h2); unpack2(acc[rp][3], l3, h3);
        float4 oA = make_float4(l0 + bz.x, l1 + bz.y, l2 + bz.z, l3 + bz.w);
        float4 oB = make_float4(h0 + bz.x, h1 + bz.y, h2 + bz.z, h3 + bz.w);
        if (resid) {
            const float4 rv = *(const float4*)&resid[rA * 256 + col];
            const float4 rw = *(const float4*)&resid[(rA + 1) * 256 + col];
            oA.x += rv.x; oA.y += rv.y; oA.z += rv.z; oA.w += rv.w;
            oB.x += rw.x; oB.y += rw.y; oB.z += rw.z; oB.w += rw.w;
        }
        *(float4*)&C[rA * 256 + col] = oA;
        *(float4*)&C[(rA + 1) * 256 + col] = oB;
    }
}

// ---------------------------------------------------------------------------
// 4) batched attention: 8 points x 64 cols per block (grid 4 x 1024).
//    M=128 rows (point,k), N=64 cols, K=256. 8x4 microtile, FFMA2 row pairs,
//    NON-duplicated w2 (float4 + bcast MOVs). dc reloaded from smem per k0
//    to keep regs < 124 -> 2 blocks/SM (4 warps/SMSP) for latency hiding.
// ---------------------------------------------------------------------------
__global__ __launch_bounds__(256) void attn_kernel(const float* __restrict__ coords,
                                                   const float* __restrict__ w1,
                                                   const float* __restrict__ b1,
                                                   const float* __restrict__ w2,
                                                   const float* __restrict__ b2) {
    __shared__ float As[16][132];     // [k][row], stride 528B (16B-aligned)
    __shared__ float Bs[16][64];      // [k][col]
    __shared__ float sdc[128 * 4];    // delta coords per row (x,y,z,pad)
    __shared__ int   sidx[128];       // neighbor ids per row
    __shared__ float sw1[3 * 256];
    __shared__ float sb1[256];

    const int t  = threadIdx.x;
    const int p0 = blockIdx.y * 8;          // first point of block
    const int cb = blockIdx.x * 64;         // column base
    const int tx = t & 15, ty = t >> 4;

    if (t < 192) ((float4*)sw1)[t] = ((const float4*)w1)[t];
    if (t < 64)  ((float4*)sb1)[t] = ((const float4*)b1)[t];
    if (t < 128) {
        const int p = t >> 4;
        const int nn = g_idx[(p0 + p) * 16 + (t & 15)];
        sidx[t] = nn;
        sdc[t * 4 + 0] = coords[nn * 3 + 0] - coords[(p0 + p) * 3 + 0];
        sdc[t * 4 + 1] = coords[nn * 3 + 1] - coords[(p0 + p) * 3 + 1];
        sdc[t * 4 + 2] = coords[nn * 3 + 2] - coords[(p0 + p) * 3 + 2];
        sdc[t * 4 + 3] = 0.0f;
    }
    __syncthreads();

    // accumulators: 4 row-pairs x 4 cols (cols cb + tx*4 + 0..3)
    u64 acc[4][4];
    {
        const float4 bA = *(const float4*)&b2[cb + tx * 4];
        const float bv[4] = {bA.x, bA.y, bA.z, bA.w};
        #pragma unroll
        for (int rp = 0; rp < 4; rp++)
            #pragma unroll
            for (int j = 0; j < 4; j++) acc[rp][j] = bcast2(bv[j]);
    }

    const float* w2p = w2 + cb;

    for (int k0 = 0; k0 < 256; k0 += 16) {
        // generate hidden tile: thread handles kk=ty, rows tx*8..+7
        // (dc reloaded from smem each k0 to keep register count low)
        {
            const int kc = k0 + ty;
            const float wx = sw1[kc], wy = sw1[256 + kc], wz = sw1[512 + kc];
            const float bb = sb1[kc];
            float h[8];
            #pragma unroll
            for (int r = 0; r < 8; r++) {
                const float4 dc = *(const float4*)&sdc[(tx * 8 + r) * 4];
                h[r] = fmaxf(fmaf(dc.z, wz, fmaf(dc.y, wy, fmaf(dc.x, wx, bb))), 0.0f);
            }
            *(float4*)&As[ty][tx * 8]     = make_float4(h[0], h[1], h[2], h[3]);
            *(float4*)&As[ty][tx * 8 + 4] = make_float4(h[4], h[5], h[6], h[7]);
        }
        // load w2 tile (16 x 64): 256 threads x 4 floats
        {
            const int kk2 = t >> 4, cq = (t & 15) * 4;
            *(float4*)&Bs[kk2][cq] = *(const float4*)&w2p[(k0 + kk2) * 256 + cq];
        }
        __syncthreads();
        #pragma unroll
        for (int kk = 0; kk < 16; kk++) {
            const ulonglong2 a01 = *(const ulonglong2*)&As[kk][ty * 8];
            const ulonglong2 a23 = *(const ulonglong2*)&As[kk][ty * 8 + 4];
            const float4 b4 = *(const float4*)&Bs[kk][tx * 4];
            const u64 b0 = bcast2(b4.x), b1v = bcast2(b4.y);
            const u64 b2v = bcast2(b4.z), b3 = bcast2(b4.w);
            fma2(acc[0][0], a01.x, b0); fma2(acc[0][1], a01.x, b1v);
            fma2(acc[0][2], a01.x, b2v); fma2(acc[0][3], a01.x, b3);
            fma2(acc[1][0], a01.y, b0); fma2(acc[1][1], a01.y, b1v);
            fma2(acc[1][2], a01.y, b2v); fma2(acc[1][3], a01.y, b3);
            fma2(acc[2][0], a23.x, b0); fma2(acc[2][1], a23.x, b1v);
            fma2(acc[2][2], a23.x, b2v); fma2(acc[2][3], a23.x, b3);
            fma2(acc[3][0], a23.y, b0); fma2(acc[3][1], a23.y, b1v);
            fma2(acc[3][2], a23.y, b2v); fma2(acc[3][3], a23.y, b3);
        }
        __syncthreads();
    }

    // ---------------- epilogue: df -> softmax(K) -> y, all in registers ----
    // warp w owns point p0+w (rows 16w..16w+15). lanes 0-15: k 0-7; 16-31: k 8-15.
    const int w = t >> 5;
    const int i = p0 + w;
    const int half = (t >> 4) & 1;
    const int kbase = half * 8;

    float th[4];
    {
        const float4 tA = *(const float4*)&g_theta[i * 256 + cb + tx * 4];
        th[0] = tA.x; th[1] = tA.y; th[2] = tA.z; th[3] = tA.w;
    }

    float mx[4];
    #pragma unroll
    for (int j = 0; j < 4; j++) mx[j] = -FLT_MAX;

    // pass 1: delta features (in place), track max over own 8 k
    #pragma unroll
    for (int rp = 0; rp < 4; rp++) {
        const int nl = sidx[w * 16 + kbase + rp * 2];
        const int nh = sidx[w * 16 + kbase + rp * 2 + 1];
        const float4 lA = *(const float4*)&g_phi[nl * 256 + cb + tx * 4];
        const float4 hA = *(const float4*)&g_phi[nh * 256 + cb + tx * 4];
        const float pl[4] = {lA.x, lA.y, lA.z, lA.w};
        const float ph[4] = {hA.x, hA.y, hA.z, hA.w};
        #pragma unroll
        for (int j = 0; j < 4; j++) {
            float lo, hi;
            unpack2(acc[rp][j], lo, hi);
            lo = lo * (th[j] - pl[j] + 1.0f) * 0.0625f;
            hi = hi * (th[j] - ph[j] + 1.0f) * 0.0625f;
            mx[j] = fmaxf(mx[j], fmaxf(lo, hi));
            acc[rp][j] = pack2(lo, hi);
        }
    }
    #pragma unroll
    for (int j = 0; j < 4; j++)
        mx[j] = fmaxf(mx[j], __shfl_xor_sync(0xffffffffu, mx[j], 16));

    float ssum[4], gac[4];
    #pragma unroll
    for (int j = 0; j < 4; j++) { ssum[j] = 0.0f; gac[j] = 0.0f; }

    // pass 2: exp + weighted g accumulation
    #pragma unroll
    for (int rp = 0; rp < 4; rp++) {
        const int nl = sidx[w * 16 + kbase + rp * 2];
        const int nh = sidx[w * 16 + kbase + rp * 2 + 1];
        const float4 lA = *(const float4*)&g_gv[nl * 256 + cb + tx * 4];
        const float4 hA = *(const float4*)&g_gv[nh * 256 + cb + tx * 4];
        const float gl[4] = {lA.x, lA.y, lA.z, lA.w};
        const float gh[4] = {hA.x, hA.y, hA.z, hA.w};
        #pragma unroll
        for (int j = 0; j < 4; j++) {
            float lo, hi;
            unpack2(acc[rp][j], lo, hi);
            const float el = __expf(lo - mx[j]);
            const float eh = __expf(hi - mx[j]);
            ssum[j] += el + eh;
            gac[j] = fmaf(el, gl[j], fmaf(eh, gh[j], gac[j]));
        }
    }
    #pragma unroll
    for (int j = 0; j < 4; j++) {
        ssum[j] += __shfl_xor_sync(0xffffffffu, ssum[j], 16);
        gac[j]  += __shfl_xor_sync(0xffffffffu, gac[j], 16);
    }

    if (half == 0) {
        float4 oA = make_float4(gac[0] / ssum[0], gac[1] / ssum[1],
                                gac[2] / ssum[2], gac[3] / ssum[3]);
        *(float4*)&g_y[i * 256 + cb + tx * 4] = oA;
    }
}

// ---------------------------------------------------------------------------
extern "C" void kernel_launch(void* const* d_in, const int* in_sizes, int n_in,
                              void* d_out, int out_size) {
    const float* coords  = (const float*)d_in[0];
    const float* feats   = (const float*)d_in[1];
    const float* theta_w = (const float*)d_in[2];
    const float* theta_b = (const float*)d_in[3];
    const float* phi_w   = (const float*)d_in[4];
    const float* phi_b   = (const float*)d_in[5];
    const float* g_w     = (const float*)d_in[6];
    const float* g_b     = (const float*)d_in[7];
    const float* pe_w1   = (const float*)d_in[8];
    const float* pe_b1   = (const float*)d_in[9];
    const float* pe_w2   = (const float*)d_in[10];
    const float* pe_b2   = (const float*)d_in[11];
    const float* W_w     = (const float*)d_in[12];
    const float* W_b     = (const float*)d_in[13];
    float* out = (float*)d_out;

    float *p_theta, *p_phi, *p_gv, *p_y;
    cudaGetSymbolAddress((void**)&p_theta, g_theta);
    cudaGetSymbolAddress((void**)&p_phi,   g_phi);
    cudaGetSymbolAddress((void**)&p_gv,    g_gv);
    cudaGetSymbolAddress((void**)&p_y,     g_y);

    prep_kernel<<<(N_PTS + 255) / 256, 256>>>(coords);
    knn_kernel<<<N_PTS, 256>>>();

    dim3 ggrid(C_CH / 64, N_PTS / 64);
    gemm64_kernel<<<ggrid, 256>>>(feats, theta_w, theta_b, nullptr, p_theta);
    gemm64_kernel<<<ggrid, 256>>>(feats, phi_w,   phi_b,   nullptr, p_phi);
    gemm64_kernel<<<ggrid, 256>>>(feats, g_w,     g_b,     nullptr, p_gv);

    dim3 agrid(4, N_PTS / 8);
    attn_kernel<<<agrid, 256>>>(coords, pe_w1, pe_b1, pe_w2, pe_b2);

    gemm64_kernel<<<ggrid, 256>>>(p_y, W_w, W_b, feats, out);
}

// round 15
// speedup vs baseline: 1.6043x; 1.4566x over previous
#include <cuda_runtime.h>
#include <float.h>

// Problem constants (fixed by reference setup_inputs)
#define N_PTS 8192
#define C_CH  256
#define KNN   16

typedef unsigned long long u64;

// ---------------- packed-fp32 (FFMA2) helpers --------------------------------
__device__ __forceinline__ void fma2(u64 &acc, u64 a, u64 b) {
    asm("fma.rn.f32x2 %0, %1, %2, %0;" : "+l"(acc) : "l"(a), "l"(b));
}
__device__ __forceinline__ u64 bcast2(float v) {
    u64 r;
    asm("mov.b64 %0, {%1, %2};" : "=l"(r) : "f"(v), "f"(v));
    return r;
}
__device__ __forceinline__ u64 pack2(float lo, float hi) {
    u64 r;
    asm("mov.b64 %0, {%1, %2};" : "=l"(r) : "f"(lo), "f"(hi));
    return r;
}
__device__ __forceinline__ void unpack2(u64 v, float &lo, float &hi) {
    asm("mov.b64 {%0, %1}, %2;" : "=f"(lo), "=f"(hi) : "l"(v));
}

// ---------------- scratch (device globals; no allocation allowed) ----------
__device__ float4 g_xyzs[N_PTS];            // x,y,z, |p|^2
__device__ int    g_idx[N_PTS * KNN];       // knn indices
__device__ float  g_theta[N_PTS * C_CH];    // feats @ theta_w + b
__device__ float  g_phi  [N_PTS * C_CH];    // feats @ phi_w + b
__device__ float  g_gv   [N_PTS * C_CH];    // feats @ g_w + b
__device__ float  g_y    [N_PTS * C_CH];    // attention output

// ---------------------------------------------------------------------------
// 1) pack coords + squared norms
// ---------------------------------------------------------------------------
__global__ __launch_bounds__(256) void prep_kernel(const float* __restrict__ coords) {
    int i = blockIdx.x * blockDim.x + threadIdx.x;
    if (i < N_PTS) {
        float x = coords[i * 3 + 0], y = coords[i * 3 + 1], z = coords[i * 3 + 2];
        g_xyzs[i] = make_float4(x, y, z, x * x + y * y + z * z);
    }
}

// ---------------------------------------------------------------------------
// 2) KNN (unchanged): one block per query point, 16x argmin w/ cached minima.
// ---------------------------------------------------------------------------
__global__ __launch_bounds__(256) void knn_kernel() {
    __shared__ float sd[N_PTS];       // 32 KB
    __shared__ float wmin[8];
    __shared__ int   warg[8];
    __shared__ int   s_win;

    const int i   = blockIdx.x;
    const int tid = threadIdx.x;
    const float4 q = g_xyzs[i];

    float lmin = FLT_MAX;
    int   larg = 0x7fffffff;
    for (int j = tid; j < N_PTS; j += 256) {
        float4 p = g_xyzs[j];
        float d = q.w + p.w - 2.0f * (q.x * p.x + q.y * p.y + q.z * p.z);
        sd[j] = d;
        if (d < lmin || (d == lmin && j < larg)) { lmin = d; larg = j; }
    }
    __syncthreads();

    const int lane = tid & 31, wid = tid >> 5;
    for (int it = 0; it < KNN; it++) {
        float v = lmin; int a = larg;
        #pragma unroll
        for (int off = 16; off > 0; off >>= 1) {
            float ov = __shfl_down_sync(0xffffffffu, v, off);
            int   oa = __shfl_down_sync(0xffffffffu, a, off);
            if (ov < v || (ov == v && oa < a)) { v = ov; a = oa; }
        }
        if (lane == 0) { wmin[wid] = v; warg[wid] = a; }
        __syncthreads();
        if (tid == 0) {
            float bv = wmin[0]; int ba = warg[0];
            #pragma unroll
            for (int w = 1; w < 8; w++)
                if (wmin[w] < bv || (wmin[w] == bv && warg[w] < ba)) { bv = wmin[w]; ba = warg[w]; }
            s_win = ba;
            g_idx[i * KNN + it] = ba;
        }
        __syncthreads();
        const int wa = s_win;
        if ((wa & 255) == tid) {
            sd[wa] = FLT_MAX;
            lmin = FLT_MAX; larg = 0x7fffffff;
            for (int j = tid; j < N_PTS; j += 256) {
                float d = sd[j];
                if (d < lmin || (d == lmin && j < larg)) { lmin = d; larg = j; }
            }
        }
    }
}

// ---------------------------------------------------------------------------
// 3) C[M,N] = A[M,256] @ B[256,N] + bias (+ residual). 64x64 tile, BK=16.
//    R9 layout + register-staged prefetch of the next k0 tile so global
//    load latency overlaps compute.
// ---------------------------------------------------------------------------
__global__ __launch_bounds__(256) void gemm64_kernel(const float* __restrict__ A,
                                                     const float* __restrict__ B,
                                                     const float* __restrict__ bias,
                                                     const float* __restrict__ resid,
                                                     float* __restrict__ C) {
    __shared__ float As[16][68];   // [k][row], stride 272B (16B-aligned)
    __shared__ float Bs[16][64];   // [k][col]

    const int tid  = threadIdx.x;
    const int row0 = blockIdx.y * 64;
    const int col0 = blockIdx.x * 64;
    const int tx = tid & 15, ty = tid >> 4;
    const int ar = tid >> 2, ak = (tid & 3) * 4;
    const int br = tid >> 4, bc = (tid & 15) * 4;

    u64 acc[2][4];                 // [row-pair][col]
    #pragma unroll
    for (int rp = 0; rp < 2; rp++)
        #pragma unroll
        for (int c = 0; c < 4; c++) acc[rp][c] = 0ull;

    // stage first tile
    float4 av = *(const float4*)&A[(row0 + ar) * 256 + ak];
    float4 bv = *(const float4*)&B[br * 256 + col0 + bc];

    for (int k0 = 0; k0 < 256; k0 += 16) {
        As[ak + 0][ar] = av.x; As[ak + 1][ar] = av.y;
        As[ak + 2][ar] = av.z; As[ak + 3][ar] = av.w;
        *(float4*)&Bs[br][bc] = bv;
        __syncthreads();
        if (k0 + 16 < 256) {               // prefetch next tile into registers
            av = *(const float4*)&A[(row0 + ar) * 256 + k0 + 16 + ak];
            bv = *(const float4*)&B[(k0 + 16 + br) * 256 + col0 + bc];
        }
        #pragma unroll
        for (int kk = 0; kk < 16; kk++) {
            const ulonglong2 a = *(const ulonglong2*)&As[kk][ty * 4];
            const float4 b4 = *(const float4*)&Bs[kk][tx * 4];
            const u64 b0 = bcast2(b4.x), b1 = bcast2(b4.y);
            const u64 b2 = bcast2(b4.z), b3 = bcast2(b4.w);
            fma2(acc[0][0], a.x, b0); fma2(acc[0][1], a.x, b1);
            fma2(acc[0][2], a.x, b2); fma2(acc[0][3], a.x, b3);
            fma2(acc[1][0], a.y, b0); fma2(acc[1][1], a.y, b1);
            fma2(acc[1][2], a.y, b2); fma2(acc[1][3], a.y, b3);
        }
        __syncthreads();
    }

    const int col = col0 + tx * 4;
    const float4 bz = *(const float4*)&bias[col];
    #pragma unroll
    for (int rp = 0; rp < 2; rp++) {
        const int rA = row0 + ty * 4 + rp * 2;
        float l0, h0, l1, h1, l2, h2, l3, h3;
        unpack2(acc[rp][0], l0, h0); unpack2(acc[rp][1], l1, h1);
        unpack2(acc[rp][2], l2, h2); unpack2(acc[rp][3], l3, h3);
        float4 oA = make_float4(l0 + bz.x, l1 + bz.y, l2 + bz.z, l3 + bz.w);
        float4 oB = make_float4(h0 + bz.x, h1 + bz.y, h2 + bz.z, h3 + bz.w);
        if (resid) {
            const float4 rv = *(const float4*)&resid[rA * 256 + col];
            const float4 rw = *(const float4*)&resid[(rA + 1) * 256 + col];
            oA.x += rv.x; oA.y += rv.y; oA.z += rv.z; oA.w += rv.w;
            oB.x += rw.x; oB.y += rw.y; oB.z += rw.z; oB.w += rw.w;
        }
        *(float4*)&C[rA * 256 + col] = oA;
        *(float4*)&C[(rA + 1) * 256 + col] = oB;
    }
}

// ---------------------------------------------------------------------------
// 4) batched attention (R9 structure): 8 points x 128 cols per block
//    (grid 2 x 1024). M=128 rows (point,k), N=128, K=256. 8x8 microtile,
//    FFMA2 row pairs. Register-staged prefetch: next w2 tile + next hidden
//    tile are produced in registers while current tile computes.
// ---------------------------------------------------------------------------
__global__ __launch_bounds__(256) void attn_kernel(const float* __restrict__ coords,
                                                   const float* __restrict__ w1,
                                                   const float* __restrict__ b1,
                                                   const float* __restrict__ w2,
                                                   const float* __restrict__ b2) {
    __shared__ float As[16][132];     // [k][row], stride 528B (16B-aligned)
    __shared__ float Bs[16][128];     // [k][col]
    __shared__ float sdc[128 * 3];    // delta coords per row
    __shared__ int   sidx[128];       // neighbor ids per row
    __shared__ float sw1[3 * 256];
    __shared__ float sb1[256];

    const int t  = threadIdx.x;
    const int p0 = blockIdx.y * 8;          // first point of block
    const int cb = blockIdx.x * 128;        // column base
    const int tx = t & 15, ty = t >> 4;

    if (t < 192) ((float4*)sw1)[t] = ((const float4*)w1)[t];
    if (t < 64)  ((float4*)sb1)[t] = ((const float4*)b1)[t];
    if (t < 128) {
        const int p = t >> 4;
        const int nn = g_idx[(p0 + p) * 16 + (t & 15)];
        sidx[t] = nn;
        sdc[t * 3 + 0] = coords[nn * 3 + 0] - coords[(p0 + p) * 3 + 0];
        sdc[t * 3 + 1] = coords[nn * 3 + 1] - coords[(p0 + p) * 3 + 1];
        sdc[t * 3 + 2] = coords[nn * 3 + 2] - coords[(p0 + p) * 3 + 2];
    }
    __syncthreads();

    // dc registers for generation rows (tx*8 .. tx*8+7); fixed across k0
    float dcx[8], dcy[8], dcz[8];
    #pragma unroll
    for (int r = 0; r < 8; r++) {
        dcx[r] = sdc[(tx * 8 + r) * 3 + 0];
        dcy[r] = sdc[(tx * 8 + r) * 3 + 1];
        dcz[r] = sdc[(tx * 8 + r) * 3 + 2];
    }

    // accumulators: 4 row-pairs x 8 cols (cols tx*4+0..3 and 64+tx*4+0..3)
    u64 acc[4][8];
    {
        const float4 bA = *(const float4*)&b2[cb + tx * 4];
        const float4 bB = *(const float4*)&b2[cb + 64 + tx * 4];
        const float bv[8] = {bA.x, bA.y, bA.z, bA.w, bB.x, bB.y, bB.z, bB.w};
        #pragma unroll
        for (int rp = 0; rp < 4; rp++)
            #pragma unroll
            for (int j = 0; j < 8; j++) acc[rp][j] = bcast2(bv[j]);
    }

    const float* w2p = w2 + cb;
    const int wk = t >> 5, wc = (t & 31) * 4;            // w2 tile slot, rows 0-7
    const int wkB = wk + 8;                              // rows 8-15 (second half)

    // stage tile k0 = 0
    float4 wv0 = *(const float4*)&w2p[wk * 256 + wc];
    float4 wv1 = *(const float4*)&w2p[wkB * 256 + wc];
    float h[8];
    {
        const float wx = sw1[ty], wy = sw1[256 + ty], wz = sw1[512 + ty];
        const float bb = sb1[ty];
        #pragma unroll
        for (int r = 0; r < 8; r++)
            h[r] = fmaxf(fmaf(dcz[r], wz, fmaf(dcy[r], wy, fmaf(dcx[r], wx, bb))), 0.0f);
    }

    for (int k0 = 0; k0 < 256; k0 += 16) {
        // commit staged tile to smem
        *(float4*)&As[ty][tx * 8]     = make_float4(h[0], h[1], h[2], h[3]);
        *(float4*)&As[ty][tx * 8 + 4] = make_float4(h[4], h[5], h[6], h[7]);
        *(float4*)&Bs[wk][wc]  = wv0;
        *(float4*)&Bs[wkB][wc] = wv1;
        __syncthreads();

        // prefetch next tile into registers (overlaps with compute below)
        if (k0 + 16 < 256) {
            wv0 = *(const float4*)&w2p[(k0 + 16 + wk) * 256 + wc];
            wv1 = *(const float4*)&w2p[(k0 + 16 + wkB) * 256 + wc];
            const int kc = k0 + 16 + ty;
            const float wx = sw1[kc], wy = sw1[256 + kc], wz = sw1[512 + kc];
            const float bb = sb1[kc];
            #pragma unroll
            for (int r = 0; r < 8; r++)
                h[r] = fmaxf(fmaf(dcz[r], wz, fmaf(dcy[r], wy, fmaf(dcx[r], wx, bb))), 0.0f);
        }

        #pragma unroll
        for (int kk = 0; kk < 16; kk++) {
            const ulonglong2 a01 = *(const ulonglong2*)&As[kk][ty * 8];
            const ulonglong2 a23 = *(const ulonglong2*)&As[kk][ty * 8 + 4];
            const float4 bA = *(const float4*)&Bs[kk][tx * 4];
            const float4 bB = *(const float4*)&Bs[kk][64 + tx * 4];
            const u64 b0 = bcast2(bA.x), b1v = bcast2(bA.y);
            const u64 b2v = bcast2(bA.z), b3 = bcast2(bA.w);
            const u64 b4 = bcast2(bB.x), b5 = bcast2(bB.y);
            const u64 b6 = bcast2(bB.z), b7 = bcast2(bB.w);
            fma2(acc[0][0], a01.x, b0); fma2(acc[0][1], a01.x, b1v);
            fma2(acc[0][2], a01.x, b2v); fma2(acc[0][3], a01.x, b3);
            fma2(acc[0][4], a01.x, b4); fma2(acc[0][5], a01.x, b5);
            fma2(acc[0][6], a01.x, b6); fma2(acc[0][7], a01.x, b7);
            fma2(acc[1][0], a01.y, b0); fma2(acc[1][1], a01.y, b1v);
            fma2(acc[1][2], a01.y, b2v); fma2(acc[1][3], a01.y, b3);
            fma2(acc[1][4], a01.y, b4); fma2(acc[1][5], a01.y, b5);
            fma2(acc[1][6], a01.y, b6); fma2(acc[1][7], a01.y, b7);
            fma2(acc[2][0], a23.x, b0); fma2(acc[2][1], a23.x, b1v);
            fma2(acc[2][2], a23.x, b2v); fma2(acc[2][3], a23.x, b3);
            fma2(acc[2][4], a23.x, b4); fma2(acc[2][5], a23.x, b5);
            fma2(acc[2][6], a23.x, b6); fma2(acc[2][7], a23.x, b7);
            fma2(acc[3][0], a23.y, b0); fma2(acc[3][1], a23.y, b1v);
            fma2(acc[3][2], a23.y, b2v); fma2(acc[3][3], a23.y, b3);
            fma2(acc[3][4], a23.y, b4); fma2(acc[3][5], a23.y, b5);
            fma2(acc[3][6], a23.y, b6); fma2(acc[3][7], a23.y, b7);
        }
        __syncthreads();
    }

    // ---------------- epilogue: df -> softmax(K) -> y, all in registers ----
    // warp w owns point p0+w (rows 16w..16w+15). lanes 0-15: k 0-7; 16-31: k 8-15.
    const int w = t >> 5;
    const int i = p0 + w;
    const int half = (t >> 4) & 1;
    const int kbase = half * 8;

    float th[8];
    {
        const float4 tA = *(const float4*)&g_theta[i * 256 + cb + tx * 4];
        const float4 tB = *(const float4*)&g_theta[i * 256 + cb + 64 + tx * 4];
        th[0] = tA.x; th[1] = tA.y; th[2] = tA.z; th[3] = tA.w;
        th[4] = tB.x; th[5] = tB.y; th[6] = tB.z; th[7] = tB.w;
    }

    float mx[8];
    #pragma unroll
    for (int j = 0; j < 8; j++) mx[j] = -FLT_MAX;

    // pass 1: delta features (in place), track max over own 8 k
    #pragma unroll
    for (int rp = 0; rp < 4; rp++) {
        const int nl = sidx[w * 16 + kbase + rp * 2];
        const int nh = sidx[w * 16 + kbase + rp * 2 + 1];
        const float4 lA = *(const float4*)&g_phi[nl * 256 + cb + tx * 4];
        const float4 lB = *(const float4*)&g_phi[nl * 256 + cb + 64 + tx * 4];
        const float4 hA = *(const float4*)&g_phi[nh * 256 + cb + tx * 4];
        const float4 hB = *(const float4*)&g_phi[nh * 256 + cb + 64 + tx * 4];
        const float pl[8] = {lA.x, lA.y, lA.z, lA.w, lB.x, lB.y, lB.z, lB.w};
        const float ph[8] = {hA.x, hA.y, hA.z, hA.w, hB.x, hB.y, hB.z, hB.w};
        #pragma unroll
        for (int j = 0; j < 8; j++) {
            float lo, hi;
            unpack2(acc[rp][j], lo, hi);
            lo = lo * (th[j] - pl[j] + 1.0f) * 0.0625f;
            hi = hi * (th[j] - ph[j] + 1.0f) * 0.0625f;
            mx[j] = fmaxf(mx[j], fmaxf(lo, hi));
            acc[rp][j] = pack2(lo, hi);
        }
    }
    #pragma unroll
    for (int j = 0; j < 8; j++)
        mx[j] = fmaxf(mx[j], __shfl_xor_sync(0xffffffffu, mx[j], 16));

    float ssum[8], gac[8];
    #pragma unroll
    for (int j = 0; j < 8; j++) { ssum[j] = 0.0f; gac[j] = 0.0f; }

    // pass 2: exp + weighted g accumulation
    #pragma unroll
    for (int rp = 0; rp < 4; rp++) {
        const int nl = sidx[w * 16 + kbase + rp * 2];
        const int nh = sidx[w * 16 + kbase + rp * 2 + 1];
        const float4 lA = *(const float4*)&g_gv[nl * 256 + cb + tx * 4];
        const float4 lB = *(const float4*)&g_gv[nl * 256 + cb + 64 + tx * 4];
        const float4 hA = *(const float4*)&g_gv[nh * 256 + cb + tx * 4];
        const float4 hB = *(const float4*)&g_gv[nh * 256 + cb + 64 + tx * 4];
        const float gl[8] = {lA.x, lA.y, lA.z, lA.w, lB.x, lB.y, lB.z, lB.w};
        const float gh[8] = {hA.x, hA.y, hA.z, hA.w, hB.x, hB.y, hB.z, hB.w};
        #pragma unroll
        for (int j = 0; j < 8; j++) {
            float lo, hi;
            unpack2(acc[rp][j], lo, hi);
            const float el = __expf(lo - mx[j]);
            const float eh = __expf(hi - mx[j]);
            ssum[j] += el + eh;
            gac[j] = fmaf(el, gl[j], fmaf(eh, gh[j], gac[j]));
        }
    }
    #pragma unroll
    for (int j = 0; j < 8; j++) {
        ssum[j] += __shfl_xor_sync(0xffffffffu, ssum[j], 16);
        gac[j]  += __shfl_xor_sync(0xffffffffu, gac[j], 16);
    }

    if (half == 0) {
        float4 oA = make_float4(gac[0] / ssum[0], gac[1] / ssum[1],
                                gac[2] / ssum[2], gac[3] / ssum[3]);
        float4 oB = make_float4(gac[4] / ssum[4], gac[5] / ssum[5],
                                gac[6] / ssum[6], gac[7] / ssum[7]);
        *(float4*)&g_y[i * 256 + cb + tx * 4] = oA;
        *(float4*)&g_y[i * 256 + cb + 64 + tx * 4] = oB;
    }
}

// ---------------------------------------------------------------------------
extern "C" void kernel_launch(void* const* d_in, const int* in_sizes, int n_in,
                              void* d_out, int out_size) {
    const float* coords  = (const float*)d_in[0];
    const float* feats   = (const float*)d_in[1];
    const float* theta_w = (const float*)d_in[2];
    const float* theta_b = (const float*)d_in[3];
    const float* phi_w   = (const float*)d_in[4];
    const float* phi_b   = (const float*)d_in[5];
    const float* g_w     = (const float*)d_in[6];
    const float* g_b     = (const float*)d_in[7];
    const float* pe_w1   = (const float*)d_in[8];
    const float* pe_b1   = (const float*)d_in[9];
    const float* pe_w2   = (const float*)d_in[10];
    const float* pe_b2   = (const float*)d_in[11];
    const float* W_w     = (const float*)d_in[12];
    const float* W_b     = (const float*)d_in[13];
    float* out = (float*)d_out;

    float *p_theta, *p_phi, *p_gv, *p_y;
    cudaGetSymbolAddress((void**)&p_theta, g_theta);
    cudaGetSymbolAddress((void**)&p_phi,   g_phi);
    cudaGetSymbolAddress((void**)&p_gv,    g_gv);
    cudaGetSymbolAddress((void**)&p_y,     g_y);

    prep_kernel<<<(N_PTS + 255) / 256, 256>>>(coords);
    knn_kernel<<<N_PTS, 256>>>();

    dim3 ggrid(C_CH / 64, N_PTS / 64);
    gemm64_kernel<<<ggrid, 256>>>(feats, theta_w, theta_b, nullptr, p_theta);
    gemm64_kernel<<<ggrid, 256>>>(feats, phi_w,   phi_b,   nullptr, p_phi);
    gemm64_kernel<<<ggrid, 256>>>(feats, g_w,     g_b,     nullptr, p_gv);

    dim3 agrid(2, N_PTS / 8);
    attn_kernel<<<agrid, 256>>>(coords, pe_w1, pe_b1, pe_w2, pe_b2);

    gemm64_kernel<<<ggrid, 256>>>(p_y, W_w, W_b, feats, out);
}